// round 3
// baseline (speedup 1.0000x reference)
#include <cuda_runtime.h>

// Problem constants
#define MODEL_DIM 1024
#define NHEAD     16
#define HDIM      64
#define BATCH     2
#define SEQ       2048
#define MROWS     (BATCH * SEQ)   // 4096

// Scratch (device globals — allocation-free per harness rules)
__device__ float g_Q[MROWS * MODEL_DIM];
__device__ float g_K[MROWS * MODEL_DIM];
__device__ float g_V[MROWS * MODEL_DIM];
__device__ float g_O[MROWS * MODEL_DIM];

// ---------------------------------------------------------------------------
// GEMM: C[M,1024] = A[M,1024] @ W[1024,1024] + bias   (all row-major fp32)
// Tile 128x128, BK=16, 256 threads, 8x8 per-thread register tile.
// ---------------------------------------------------------------------------
__global__ __launch_bounds__(256) void gemm_bias_kernel(
    const float* __restrict__ A, const float* __restrict__ W,
    const float* __restrict__ bias, float* __restrict__ C) {
    __shared__ float As[16][132];   // A tile stored transposed [k][m], padded
    __shared__ float Bs[16][128];   // W tile natural [k][n]

    const int tid = threadIdx.x;
    const int tx = tid & 15;        // 0..15 -> N direction
    const int ty = tid >> 4;        // 0..15 -> M direction
    const int brow = blockIdx.y * 128;
    const int bcol = blockIdx.x * 128;

    float acc[8][8];
#pragma unroll
    for (int i = 0; i < 8; i++)
#pragma unroll
        for (int j = 0; j < 8; j++) acc[i][j] = 0.f;

    for (int k0 = 0; k0 < MODEL_DIM; k0 += 16) {
        // Load A tile (128x16) transposed into As
#pragma unroll
        for (int i = 0; i < 2; i++) {
            int f = tid + i * 256;          // 0..511
            int r = f >> 2;                 // 0..127
            int kc = (f & 3) * 4;           // 0,4,8,12
            float4 a = *(const float4*)(A + (size_t)(brow + r) * MODEL_DIM + k0 + kc);
            As[kc + 0][r] = a.x; As[kc + 1][r] = a.y;
            As[kc + 2][r] = a.z; As[kc + 3][r] = a.w;
        }
        // Load W tile (16x128)
#pragma unroll
        for (int i = 0; i < 2; i++) {
            int f = tid + i * 256;
            int r = f >> 5;                 // 0..15
            int c = (f & 31) * 4;           // 0..124
            *(float4*)(&Bs[r][c]) =
                *(const float4*)(W + (size_t)(k0 + r) * MODEL_DIM + bcol + c);
        }
        __syncthreads();

#pragma unroll
        for (int k = 0; k < 16; k++) {
            float4 a0 = *(const float4*)(&As[k][ty * 4]);
            float4 a1 = *(const float4*)(&As[k][64 + ty * 4]);
            float4 b0 = *(const float4*)(&Bs[k][tx * 4]);
            float4 b1 = *(const float4*)(&Bs[k][64 + tx * 4]);
            float av[8] = {a0.x, a0.y, a0.z, a0.w, a1.x, a1.y, a1.z, a1.w};
            float bv[8] = {b0.x, b0.y, b0.z, b0.w, b1.x, b1.y, b1.z, b1.w};
#pragma unroll
            for (int i = 0; i < 8; i++)
#pragma unroll
                for (int j = 0; j < 8; j++) acc[i][j] += av[i] * bv[j];
        }
        __syncthreads();
    }

    // Bias (per-column), then store
    float4 bb0 = *(const float4*)(bias + bcol + tx * 4);
    float4 bb1 = *(const float4*)(bias + bcol + 64 + tx * 4);
    float bv[8] = {bb0.x, bb0.y, bb0.z, bb0.w, bb1.x, bb1.y, bb1.z, bb1.w};

#pragma unroll
    for (int ii = 0; ii < 2; ii++)
#pragma unroll
        for (int i = 0; i < 4; i++) {
            int r = brow + ii * 64 + ty * 4 + i;
#pragma unroll
            for (int jj = 0; jj < 2; jj++) {
                int c = bcol + jj * 64 + tx * 4;
                float4 o;
                o.x = acc[ii * 4 + i][jj * 4 + 0] + bv[jj * 4 + 0];
                o.y = acc[ii * 4 + i][jj * 4 + 1] + bv[jj * 4 + 1];
                o.z = acc[ii * 4 + i][jj * 4 + 2] + bv[jj * 4 + 2];
                o.w = acc[ii * 4 + i][jj * 4 + 3] + bv[jj * 4 + 3];
                *(float4*)(C + (size_t)r * MODEL_DIM + c) = o;
            }
        }
}

// ---------------------------------------------------------------------------
// Flash attention, fp32. One block = (64 query rows) x (one b,h pair).
// 256 threads; thread (ty,tx) owns score rows ty*4..+3, cols tx*4..+3.
// Smem: Qt transposed [d][row] (stride 68), Kt transposed [d][col] (stride 68,
// reused as P [row][col]), V natural [row][d] (stride 68).
// ---------------------------------------------------------------------------
#define ATT_STRIDE 68
#define ATT_SMEM_BYTES (3 * 64 * ATT_STRIDE * 4)

__global__ __launch_bounds__(256) void attn_kernel(const int* __restrict__ mask) {
    extern __shared__ float sm[];
    float* Qt = sm;                       // [64][68] (d-major)
    float* Kt = sm + 64 * ATT_STRIDE;     // [64][68] (d-major), reused as P
    float* Vs = sm + 2 * 64 * ATT_STRIDE; // [64][68] (row-major)

    const int tid = threadIdx.x;
    const int tx = tid & 15;
    const int ty = tid >> 4;
    const int qt = blockIdx.x;            // query tile 0..31
    const int bh = blockIdx.y;            // 0..31
    const int b = bh >> 4, h = bh & 15;

    const float* Qg = g_Q + ((size_t)(b * SEQ + qt * 64)) * MODEL_DIM + h * HDIM;
    const float* Kg = g_K + ((size_t)(b * SEQ)) * MODEL_DIM + h * HDIM;
    const float* Vg = g_V + ((size_t)(b * SEQ)) * MODEL_DIM + h * HDIM;

    // Load Q tile (64 rows x 64 dims), store transposed
#pragma unroll
    for (int i = 0; i < 4; i++) {
        int f = tid + i * 256;            // 0..1023
        int r = f >> 4;                   // 0..63
        int d = (f & 15) * 4;             // 0..60
        float4 q = *(const float4*)(Qg + (size_t)r * MODEL_DIM + d);
        Qt[(d + 0) * ATT_STRIDE + r] = q.x;
        Qt[(d + 1) * ATT_STRIDE + r] = q.y;
        Qt[(d + 2) * ATT_STRIDE + r] = q.z;
        Qt[(d + 3) * ATT_STRIDE + r] = q.w;
    }

    float m_i[4], l_i[4], o[4][4];
#pragma unroll
    for (int i = 0; i < 4; i++) {
        m_i[i] = -1e30f; l_i[i] = 0.f;
#pragma unroll
        for (int j = 0; j < 4; j++) o[i][j] = 0.f;
    }

    for (int kt = 0; kt < SEQ / 64; kt++) {
        __syncthreads();  // protect Kt(P)/Vs from previous iteration's readers
        // Load K tile transposed + V tile natural
#pragma unroll
        for (int i = 0; i < 4; i++) {
            int f = tid + i * 256;
            int r = f >> 4;
            int d = (f & 15) * 4;
            float4 kv = *(const float4*)(Kg + (size_t)(kt * 64 + r) * MODEL_DIM + d);
            Kt[(d + 0) * ATT_STRIDE + r] = kv.x;
            Kt[(d + 1) * ATT_STRIDE + r] = kv.y;
            Kt[(d + 2) * ATT_STRIDE + r] = kv.z;
            Kt[(d + 3) * ATT_STRIDE + r] = kv.w;
            float4 vv = *(const float4*)(Vg + (size_t)(kt * 64 + r) * MODEL_DIM + d);
            *(float4*)(&Vs[r * ATT_STRIDE + d]) = vv;
        }
        __syncthreads();

        // Scores: S[i][j] = sum_d Qt[d][row_i] * Kt[d][col_j]
        float s[4][4];
#pragma unroll
        for (int i = 0; i < 4; i++)
#pragma unroll
            for (int j = 0; j < 4; j++) s[i][j] = 0.f;

#pragma unroll
        for (int d4 = 0; d4 < 64; d4 += 4) {
#pragma unroll
            for (int u = 0; u < 4; u++) {
                float4 a = *(const float4*)(&Qt[(d4 + u) * ATT_STRIDE + ty * 4]);
                float4 bq = *(const float4*)(&Kt[(d4 + u) * ATT_STRIDE + tx * 4]);
                float av[4] = {a.x, a.y, a.z, a.w};
                float bw[4] = {bq.x, bq.y, bq.z, bq.w};
#pragma unroll
                for (int i = 0; i < 4; i++)
#pragma unroll
                    for (int j = 0; j < 4; j++) s[i][j] += av[i] * bw[j];
            }
        }

        // Scale + mask
        const float scale = 0.125f;  // 1/sqrt(64)
#pragma unroll
        for (int i = 0; i < 4; i++) {
            int4 mv = *(const int4*)(mask + (size_t)(qt * 64 + ty * 4 + i) * SEQ
                                          + kt * 64 + tx * 4);
            s[i][0] = mv.x ? s[i][0] * scale : -1e9f;
            s[i][1] = mv.y ? s[i][1] * scale : -1e9f;
            s[i][2] = mv.z ? s[i][2] * scale : -1e9f;
            s[i][3] = mv.w ? s[i][3] * scale : -1e9f;
        }

        // Online softmax (row groups = 16 lanes sharing ty)
#pragma unroll
        for (int i = 0; i < 4; i++) {
            float mx = fmaxf(fmaxf(s[i][0], s[i][1]), fmaxf(s[i][2], s[i][3]));
#pragma unroll
            for (int off = 8; off >= 1; off >>= 1)
                mx = fmaxf(mx, __shfl_xor_sync(0xffffffffu, mx, off));
            float mnew = fmaxf(m_i[i], mx);
            float alpha = __expf(m_i[i] - mnew);
            float rs = 0.f;
#pragma unroll
            for (int j = 0; j < 4; j++) {
                s[i][j] = __expf(s[i][j] - mnew);
                rs += s[i][j];
            }
#pragma unroll
            for (int off = 8; off >= 1; off >>= 1)
                rs += __shfl_xor_sync(0xffffffffu, rs, off);
            l_i[i] = l_i[i] * alpha + rs;
            m_i[i] = mnew;
#pragma unroll
            for (int j = 0; j < 4; j++) o[i][j] *= alpha;
        }

        __syncthreads();  // everyone done reading Kt
        // Store P into Kt's memory as [row][col], stride 68
        float* Ps = Kt;
#pragma unroll
        for (int i = 0; i < 4; i++)
            *(float4*)(&Ps[(ty * 4 + i) * ATT_STRIDE + tx * 4]) =
                make_float4(s[i][0], s[i][1], s[i][2], s[i][3]);
        __syncthreads();

        // O[i][c] += sum_j P[row_i][j] * V[j][c]
#pragma unroll
        for (int j4 = 0; j4 < 64; j4 += 4) {
            float4 p[4];
#pragma unroll
            for (int i = 0; i < 4; i++)
                p[i] = *(const float4*)(&Ps[(ty * 4 + i) * ATT_STRIDE + j4]);
            float4 v[4];
#pragma unroll
            for (int u = 0; u < 4; u++)
                v[u] = *(const float4*)(&Vs[(j4 + u) * ATT_STRIDE + tx * 4]);
#pragma unroll
            for (int i = 0; i < 4; i++) {
                float pv[4] = {p[i].x, p[i].y, p[i].z, p[i].w};
#pragma unroll
                for (int u = 0; u < 4; u++) {
                    o[i][0] += pv[u] * v[u].x;
                    o[i][1] += pv[u] * v[u].y;
                    o[i][2] += pv[u] * v[u].z;
                    o[i][3] += pv[u] * v[u].w;
                }
            }
        }
    }

    // Epilogue: divide by l, write to g_O (interleaved head layout)
    float* Og = g_O + ((size_t)(b * SEQ + qt * 64)) * MODEL_DIM + h * HDIM;
#pragma unroll
    for (int i = 0; i < 4; i++) {
        float inv = 1.f / l_i[i];
        float4 r = make_float4(o[i][0] * inv, o[i][1] * inv,
                               o[i][2] * inv, o[i][3] * inv);
        *(float4*)(Og + (size_t)(ty * 4 + i) * MODEL_DIM + tx * 4) = r;
    }
}

// ---------------------------------------------------------------------------
// Launch
// ---------------------------------------------------------------------------
extern "C" void kernel_launch(void* const* d_in, const int* in_sizes, int n_in,
                              void* d_out, int out_size) {
    const float* q   = (const float*)d_in[0];
    const float* k   = (const float*)d_in[1];
    const float* v   = (const float*)d_in[2];
    const int*   msk = (const int*)  d_in[3];
    const float* w_q = (const float*)d_in[4];
    const float* b_q = (const float*)d_in[5];
    const float* w_k = (const float*)d_in[6];
    const float* b_k = (const float*)d_in[7];
    const float* w_v = (const float*)d_in[8];
    const float* b_v = (const float*)d_in[9];
    const float* w_o = (const float*)d_in[10];
    const float* b_o = (const float*)d_in[11];
    float* out = (float*)d_out;

    float *pQ, *pK, *pV, *pO;
    cudaGetSymbolAddress((void**)&pQ, g_Q);
    cudaGetSymbolAddress((void**)&pK, g_K);
    cudaGetSymbolAddress((void**)&pV, g_V);
    cudaGetSymbolAddress((void**)&pO, g_O);

    static bool attr_set = false;
    if (!attr_set) {
        cudaFuncSetAttribute(attn_kernel,
                             cudaFuncAttributeMaxDynamicSharedMemorySize,
                             ATT_SMEM_BYTES);
        attr_set = true;
    }

    dim3 gblock(256);
    dim3 ggrid(MODEL_DIM / 128, MROWS / 128);  // (8, 32)

    gemm_bias_kernel<<<ggrid, gblock>>>(q, w_q, b_q, pQ);
    gemm_bias_kernel<<<ggrid, gblock>>>(k, w_k, b_k, pK);
    gemm_bias_kernel<<<ggrid, gblock>>>(v, w_v, b_v, pV);

    dim3 agrid(SEQ / 64, BATCH * NHEAD);       // (32, 32)
    attn_kernel<<<agrid, gblock, ATT_SMEM_BYTES>>>(msk);

    gemm_bias_kernel<<<ggrid, gblock>>>(pO, w_o, b_o, out);
}

// round 7
// speedup vs baseline: 1.2980x; 1.2980x over previous
#include <cuda_runtime.h>
#include <cuda_bf16.h>
#include <cstdint>

// Problem constants
#define MODEL_DIM 1024
#define NHEAD     16
#define HDIM      64
#define BATCH     2
#define SEQ       2048
#define MROWS     (BATCH * SEQ)   // 4096

// ===========================================================================
// Scratch (device globals — allocation-free per harness rules)
// ===========================================================================
__device__ float g_Q[MROWS * MODEL_DIM];
__device__ float g_K[MROWS * MODEL_DIM];
__device__ float g_V[MROWS * MODEL_DIM];
__device__ float g_O[MROWS * MODEL_DIM];
// bf16 split buffers (reused sequentially across the 4 GEMMs)
__device__ __nv_bfloat16 g_Ahi[MROWS * MODEL_DIM];
__device__ __nv_bfloat16 g_Alo[MROWS * MODEL_DIM];
__device__ __nv_bfloat16 g_Bhi[MODEL_DIM * MODEL_DIM];   // W^T hi  [n][k]
__device__ __nv_bfloat16 g_Blo[MODEL_DIM * MODEL_DIM];   // W^T lo  [n][k]

// ===========================================================================
// Helpers (base sm_103 ISA only: ldmatrix + mma.sync, no tcgen05)
// ===========================================================================
__device__ __forceinline__ uint32_t smem_u32(const void* p) {
    uint32_t a;
    asm("{ .reg .u64 t; cvta.to.shared.u64 t, %1; cvt.u32.u64 %0, t; }"
        : "=r"(a) : "l"(p));
    return a;
}

#define SMEM_SWIZZLE_128B(o) ((o) ^ (((o) >> 3) & 0x70))

__device__ __forceinline__ void ldsm_x4(uint32_t* r, uint32_t addr) {
    asm volatile("ldmatrix.sync.aligned.m8n8.x4.shared.b16 {%0,%1,%2,%3}, [%4];"
                 : "=r"(r[0]), "=r"(r[1]), "=r"(r[2]), "=r"(r[3]) : "r"(addr));
}
__device__ __forceinline__ void ldsm_x2(uint32_t* r, uint32_t addr) {
    asm volatile("ldmatrix.sync.aligned.m8n8.x2.shared.b16 {%0,%1}, [%2];"
                 : "=r"(r[0]), "=r"(r[1]) : "r"(addr));
}
__device__ __forceinline__ void mma16816(float* c, const uint32_t* a,
                                         const uint32_t* b) {
    asm volatile(
        "mma.sync.aligned.m16n8k16.row.col.f32.bf16.bf16.f32 "
        "{%0,%1,%2,%3}, {%4,%5,%6,%7}, {%8,%9}, {%0,%1,%2,%3};"
        : "+f"(c[0]), "+f"(c[1]), "+f"(c[2]), "+f"(c[3])
        : "r"(a[0]), "r"(a[1]), "r"(a[2]), "r"(a[3]), "r"(b[0]), "r"(b[1]));
}

// ===========================================================================
// fp32 -> bf16 hi/lo split for activations (layout preserved)
// ===========================================================================
__global__ __launch_bounds__(256) void conv_act(
    const float4* __restrict__ X,
    __nv_bfloat162* __restrict__ hi2, __nv_bfloat162* __restrict__ lo2) {
    int i = blockIdx.x * 256 + threadIdx.x;   // grid sized exactly: n/4 threads
    float4 x = X[i];
    __nv_bfloat16 h0 = __float2bfloat16_rn(x.x);
    __nv_bfloat16 h1 = __float2bfloat16_rn(x.y);
    __nv_bfloat16 h2 = __float2bfloat16_rn(x.z);
    __nv_bfloat16 h3 = __float2bfloat16_rn(x.w);
    __nv_bfloat16 l0 = __float2bfloat16_rn(x.x - __bfloat162float(h0));
    __nv_bfloat16 l1 = __float2bfloat16_rn(x.y - __bfloat162float(h1));
    __nv_bfloat16 l2 = __float2bfloat16_rn(x.z - __bfloat162float(h2));
    __nv_bfloat16 l3 = __float2bfloat16_rn(x.w - __bfloat162float(h3));
    hi2[2 * i + 0] = __nv_bfloat162(h0, h1);
    hi2[2 * i + 1] = __nv_bfloat162(h2, h3);
    lo2[2 * i + 0] = __nv_bfloat162(l0, l1);
    lo2[2 * i + 1] = __nv_bfloat162(l2, l3);
}

// fp32 W[k][n] -> transposed bf16 hi/lo Wt[n][k]  (smem tile transpose)
__global__ __launch_bounds__(256) void conv_wt(
    const float* __restrict__ W,
    __nv_bfloat16* __restrict__ Thi, __nv_bfloat16* __restrict__ Tlo) {
    __shared__ float t[32][33];
    int n0 = blockIdx.x * 32, k0 = blockIdx.y * 32;
    int tx = threadIdx.x, ty = threadIdx.y;   // block (32, 8)
#pragma unroll
    for (int i = 0; i < 4; i++)
        t[ty + 8 * i][tx] = W[(size_t)(k0 + ty + 8 * i) * MODEL_DIM + n0 + tx];
    __syncthreads();
#pragma unroll
    for (int i = 0; i < 4; i++) {
        float x = t[tx][ty + 8 * i];          // t[k_local][n_local]
        __nv_bfloat16 h = __float2bfloat16_rn(x);
        __nv_bfloat16 l = __float2bfloat16_rn(x - __bfloat162float(h));
        size_t off = (size_t)(n0 + ty + 8 * i) * MODEL_DIM + k0 + tx;
        Thi[off] = h;
        Tlo[off] = l;
    }
}

// ===========================================================================
// HMMA GEMM: C[M,1024] = A[M,1024] @ W[1024,1024] + bias
// bf16x3 split: Ahi*Bhi + Ahi*Blo + Alo*Bhi, fp32 accumulate in registers.
// CTA 128x128, BK=64, 256 threads (8 warps, warp tile 64x32), SW128 smem.
// ===========================================================================
#define G_OFF_AH   0
#define G_OFF_AL   16384
#define G_OFF_BH   32768
#define G_OFF_BL   49152
#define G_SMEM_TOTAL 65536

// Load a 128-row x 64-col bf16 tile (128 B/row) global -> SW128 smem
__device__ __forceinline__ void load_tile_bf16(
    char* smem, int dst_off, const __nv_bfloat16* __restrict__ src,
    int row0, int k0, int tid) {
#pragma unroll
    for (int it = 0; it < 4; it++) {
        int t = tid + it * 256;               // 0..1023
        int row = t >> 3;                     // 0..127
        int seg = t & 7;                      // 0..7 (16B each)
        uint4 v = *(const uint4*)(src + (size_t)(row0 + row) * MODEL_DIM + k0 + seg * 8);
        *(uint4*)(smem + dst_off + SMEM_SWIZZLE_128B(row * 128 + seg * 16)) = v;
    }
}

__global__ __launch_bounds__(256) void gemm_tc(
    const __nv_bfloat16* __restrict__ Ahi, const __nv_bfloat16* __restrict__ Alo,
    const __nv_bfloat16* __restrict__ Bhi, const __nv_bfloat16* __restrict__ Blo,
    const float* __restrict__ bias, float* __restrict__ C) {
    extern __shared__ char smem[];
    uint32_t sb = smem_u32(smem);
    const int tid = threadIdx.x;
    const int wid = tid >> 5;
    const int lane = tid & 31;
    const int warp_m = wid >> 2;              // 0..1  -> 64-row slab
    const int warp_n = wid & 3;               // 0..3  -> 32-col slab
    const int m0 = blockIdx.y * 128;
    const int n0 = blockIdx.x * 128;

    float acc[4][4][4];                       // [mt][nt][frag]
#pragma unroll
    for (int i = 0; i < 4; i++)
#pragma unroll
        for (int j = 0; j < 4; j++)
#pragma unroll
            for (int f = 0; f < 4; f++) acc[i][j][f] = 0.f;

    // Per-lane ldmatrix byte offsets (within a tile), before swizzle:
    //  A x4: lanes 0-15 -> rows (m_base + lane&15) at kb; lanes 16-31 -> same rows, kb+8
    const int a_row = lane & 15;
    const int a_kb = (lane >> 4) << 4;        // 0 or 16 bytes (8 bf16)
    //  B x2: lanes 0-7 -> rows (n_base+lane&7) at kb; lanes 8-15 -> kb+8
    const int b_row = lane & 7;
    const int b_kb = ((lane >> 3) & 1) << 4;  // 0 or 16 bytes

    for (int ck = 0; ck < MODEL_DIM / 64; ck++) {
        int k0 = ck * 64;
        load_tile_bf16(smem, G_OFF_AH, Ahi, m0, k0, tid);
        load_tile_bf16(smem, G_OFF_AL, Alo, m0, k0, tid);
        load_tile_bf16(smem, G_OFF_BH, Bhi, n0, k0, tid);
        load_tile_bf16(smem, G_OFF_BL, Blo, n0, k0, tid);
        __syncthreads();

#pragma unroll
        for (int ks = 0; ks < 4; ks++) {      // four k16 steps within BK=64
            uint32_t ah[4][4], al[4][4], bh[4][2], bl[4][2];
#pragma unroll
            for (int mt = 0; mt < 4; mt++) {
                int row = warp_m * 64 + mt * 16 + a_row;
                int boff = row * 128 + ks * 32 + a_kb;
                uint32_t sw = SMEM_SWIZZLE_128B(boff);
                ldsm_x4(ah[mt], sb + G_OFF_AH + sw);
                ldsm_x4(al[mt], sb + G_OFF_AL + sw);
            }
#pragma unroll
            for (int nt = 0; nt < 4; nt++) {
                int row = warp_n * 32 + nt * 8 + b_row;
                int boff = row * 128 + ks * 32 + b_kb;
                uint32_t sw = SMEM_SWIZZLE_128B(boff);
                ldsm_x2(bh[nt], sb + G_OFF_BH + sw);
                ldsm_x2(bl[nt], sb + G_OFF_BL + sw);
            }
#pragma unroll
            for (int mt = 0; mt < 4; mt++)
#pragma unroll
                for (int nt = 0; nt < 4; nt++) {
                    mma16816(acc[mt][nt], ah[mt], bh[nt]);
                    mma16816(acc[mt][nt], ah[mt], bl[nt]);
                    mma16816(acc[mt][nt], al[mt], bh[nt]);
                }
        }
        __syncthreads();
    }

    // Epilogue: accumulator frag layout c0,c1=(row g, col 2t,2t+1), c2,c3=row g+8
    const int g = lane >> 2;
    const int tq = (lane & 3) * 2;
#pragma unroll
    for (int mt = 0; mt < 4; mt++)
#pragma unroll
        for (int nt = 0; nt < 4; nt++) {
            int m = m0 + warp_m * 64 + mt * 16 + g;
            int n = n0 + warp_n * 32 + nt * 8 + tq;
            float2 bb = *(const float2*)(bias + n);
            float2 v0 = make_float2(acc[mt][nt][0] + bb.x, acc[mt][nt][1] + bb.y);
            float2 v1 = make_float2(acc[mt][nt][2] + bb.x, acc[mt][nt][3] + bb.y);
            *(float2*)(C + (size_t)m * MODEL_DIM + n) = v0;
            *(float2*)(C + (size_t)(m + 8) * MODEL_DIM + n) = v1;
        }
}

// ===========================================================================
// Flash attention, fp32. One block = 64 query rows x one (b,h).
// Qt/Kt stored d-major with a granule-rotated layout to fix the 16-way
// bank conflict on transposed stores:
//   offset(d, r) = d*68 + ((r + 4*(d>>2)) & 63)   -> 2-way store conflicts,
//   compute loads stay float4-aligned & conflict-free.
// ===========================================================================
#define ATT_STRIDE 68
#define ATT_SMEM_BYTES (3 * 64 * ATT_STRIDE * 4)
#define QKOFF(d, r) ((d) * ATT_STRIDE + (((r) + ((((d) >> 2)) << 2)) & 63))

__global__ __launch_bounds__(256) void attn_kernel(const int* __restrict__ mask) {
    extern __shared__ float sm[];
    float* Qt = sm;                       // [64][68] d-major, rotated
    float* Kt = sm + 64 * ATT_STRIDE;     // [64][68] d-major, rotated; reused as P
    float* Vs = sm + 2 * 64 * ATT_STRIDE; // [64][68] row-major

    const int tid = threadIdx.x;
    const int tx = tid & 15;
    const int ty = tid >> 4;
    const int qt = blockIdx.x;
    const int bh = blockIdx.y;
    const int b = bh >> 4, h = bh & 15;

    const float* Qg = g_Q + ((size_t)(b * SEQ + qt * 64)) * MODEL_DIM + h * HDIM;
    const float* Kg = g_K + ((size_t)(b * SEQ)) * MODEL_DIM + h * HDIM;
    const float* Vg = g_V + ((size_t)(b * SEQ)) * MODEL_DIM + h * HDIM;

#pragma unroll
    for (int i = 0; i < 4; i++) {
        int f = tid + i * 256;
        int r = f >> 4;
        int d = (f & 15) * 4;
        float4 q = *(const float4*)(Qg + (size_t)r * MODEL_DIM + d);
        Qt[QKOFF(d + 0, r)] = q.x;
        Qt[QKOFF(d + 1, r)] = q.y;
        Qt[QKOFF(d + 2, r)] = q.z;
        Qt[QKOFF(d + 3, r)] = q.w;
    }

    float m_i[4], l_i[4], o[4][4];
#pragma unroll
    for (int i = 0; i < 4; i++) {
        m_i[i] = -1e30f; l_i[i] = 0.f;
#pragma unroll
        for (int j = 0; j < 4; j++) o[i][j] = 0.f;
    }

    for (int kt = 0; kt < SEQ / 64; kt++) {
        __syncthreads();
#pragma unroll
        for (int i = 0; i < 4; i++) {
            int f = tid + i * 256;
            int r = f >> 4;
            int d = (f & 15) * 4;
            float4 kv = *(const float4*)(Kg + (size_t)(kt * 64 + r) * MODEL_DIM + d);
            Kt[QKOFF(d + 0, r)] = kv.x;
            Kt[QKOFF(d + 1, r)] = kv.y;
            Kt[QKOFF(d + 2, r)] = kv.z;
            Kt[QKOFF(d + 3, r)] = kv.w;
            float4 vv = *(const float4*)(Vg + (size_t)(kt * 64 + r) * MODEL_DIM + d);
            *(float4*)(&Vs[r * ATT_STRIDE + d]) = vv;
        }
        __syncthreads();

        float s[4][4];
#pragma unroll
        for (int i = 0; i < 4; i++)
#pragma unroll
            for (int j = 0; j < 4; j++) s[i][j] = 0.f;

#pragma unroll
        for (int d4 = 0; d4 < 64; d4 += 4) {
#pragma unroll
            for (int u = 0; u < 4; u++) {
                float4 a = *(const float4*)(&Qt[QKOFF(d4 + u, ty * 4)]);
                float4 bq = *(const float4*)(&Kt[QKOFF(d4 + u, tx * 4)]);
                float av[4] = {a.x, a.y, a.z, a.w};
                float bw[4] = {bq.x, bq.y, bq.z, bq.w};
#pragma unroll
                for (int i = 0; i < 4; i++)
#pragma unroll
                    for (int j = 0; j < 4; j++) s[i][j] += av[i] * bw[j];
            }
        }

        const float scale = 0.125f;  // 1/sqrt(64)
#pragma unroll
        for (int i = 0; i < 4; i++) {
            int4 mv = *(const int4*)(mask + (size_t)(qt * 64 + ty * 4 + i) * SEQ
                                          + kt * 64 + tx * 4);
            s[i][0] = mv.x ? s[i][0] * scale : -1e9f;
            s[i][1] = mv.y ? s[i][1] * scale : -1e9f;
            s[i][2] = mv.z ? s[i][2] * scale : -1e9f;
            s[i][3] = mv.w ? s[i][3] * scale : -1e9f;
        }

#pragma unroll
        for (int i = 0; i < 4; i++) {
            float mx = fmaxf(fmaxf(s[i][0], s[i][1]), fmaxf(s[i][2], s[i][3]));
#pragma unroll
            for (int off = 8; off >= 1; off >>= 1)
                mx = fmaxf(mx, __shfl_xor_sync(0xffffffffu, mx, off));
            float mnew = fmaxf(m_i[i], mx);
            float alpha = __expf(m_i[i] - mnew);
            float rs = 0.f;
#pragma unroll
            for (int j = 0; j < 4; j++) {
                s[i][j] = __expf(s[i][j] - mnew);
                rs += s[i][j];
            }
#pragma unroll
            for (int off = 8; off >= 1; off >>= 1)
                rs += __shfl_xor_sync(0xffffffffu, rs, off);
            l_i[i] = l_i[i] * alpha + rs;
            m_i[i] = mnew;
#pragma unroll
            for (int j = 0; j < 4; j++) o[i][j] *= alpha;
        }

        __syncthreads();
        float* Ps = Kt;
#pragma unroll
        for (int i = 0; i < 4; i++)
            *(float4*)(&Ps[(ty * 4 + i) * ATT_STRIDE + tx * 4]) =
                make_float4(s[i][0], s[i][1], s[i][2], s[i][3]);
        __syncthreads();

#pragma unroll
        for (int j4 = 0; j4 < 64; j4 += 4) {
            float4 p[4];
#pragma unroll
            for (int i = 0; i < 4; i++)
                p[i] = *(const float4*)(&Ps[(ty * 4 + i) * ATT_STRIDE + j4]);
            float4 v[4];
#pragma unroll
            for (int u = 0; u < 4; u++)
                v[u] = *(const float4*)(&Vs[(j4 + u) * ATT_STRIDE + tx * 4]);
#pragma unroll
            for (int i = 0; i < 4; i++) {
                float pv[4] = {p[i].x, p[i].y, p[i].z, p[i].w};
#pragma unroll
                for (int u = 0; u < 4; u++) {
                    o[i][0] += pv[u] * v[u].x;
                    o[i][1] += pv[u] * v[u].y;
                    o[i][2] += pv[u] * v[u].z;
                    o[i][3] += pv[u] * v[u].w;
                }
            }
        }
    }

    float* Og = g_O + ((size_t)(b * SEQ + qt * 64)) * MODEL_DIM + h * HDIM;
#pragma unroll
    for (int i = 0; i < 4; i++) {
        float inv = 1.f / l_i[i];
        float4 r = make_float4(o[i][0] * inv, o[i][1] * inv,
                               o[i][2] * inv, o[i][3] * inv);
        *(float4*)(Og + (size_t)(ty * 4 + i) * MODEL_DIM + tx * 4) = r;
    }
}

// ===========================================================================
// Launch
// ===========================================================================
extern "C" void kernel_launch(void* const* d_in, const int* in_sizes, int n_in,
                              void* d_out, int out_size) {
    const float* q   = (const float*)d_in[0];
    const float* k   = (const float*)d_in[1];
    const float* v   = (const float*)d_in[2];
    const int*   msk = (const int*)  d_in[3];
    const float* w_q = (const float*)d_in[4];
    const float* b_q = (const float*)d_in[5];
    const float* w_k = (const float*)d_in[6];
    const float* b_k = (const float*)d_in[7];
    const float* w_v = (const float*)d_in[8];
    const float* b_v = (const float*)d_in[9];
    const float* w_o = (const float*)d_in[10];
    const float* b_o = (const float*)d_in[11];
    float* out = (float*)d_out;

    float *pQ, *pK, *pV, *pO;
    __nv_bfloat16 *pAhi, *pAlo, *pBhi, *pBlo;
    cudaGetSymbolAddress((void**)&pQ, g_Q);
    cudaGetSymbolAddress((void**)&pK, g_K);
    cudaGetSymbolAddress((void**)&pV, g_V);
    cudaGetSymbolAddress((void**)&pO, g_O);
    cudaGetSymbolAddress((void**)&pAhi, g_Ahi);
    cudaGetSymbolAddress((void**)&pAlo, g_Alo);
    cudaGetSymbolAddress((void**)&pBhi, g_Bhi);
    cudaGetSymbolAddress((void**)&pBlo, g_Blo);

    cudaFuncSetAttribute(attn_kernel,
                         cudaFuncAttributeMaxDynamicSharedMemorySize,
                         ATT_SMEM_BYTES);
    cudaFuncSetAttribute(gemm_tc,
                         cudaFuncAttributeMaxDynamicSharedMemorySize,
                         G_SMEM_TOTAL);

    const int act_blocks = (MROWS * MODEL_DIM / 4) / 256;   // 4096
    dim3 wt_grid(MODEL_DIM / 32, MODEL_DIM / 32);           // (32, 32)
    dim3 wt_block(32, 8);
    dim3 g_grid(MODEL_DIM / 128, MROWS / 128);              // (8, 32)

    // Q projection
    conv_act<<<act_blocks, 256>>>((const float4*)q,
                                  (__nv_bfloat162*)pAhi, (__nv_bfloat162*)pAlo);
    conv_wt<<<wt_grid, wt_block>>>(w_q, pBhi, pBlo);
    gemm_tc<<<g_grid, 256, G_SMEM_TOTAL>>>(pAhi, pAlo, pBhi, pBlo, b_q, pQ);
    // K projection
    conv_act<<<act_blocks, 256>>>((const float4*)k,
                                  (__nv_bfloat162*)pAhi, (__nv_bfloat162*)pAlo);
    conv_wt<<<wt_grid, wt_block>>>(w_k, pBhi, pBlo);
    gemm_tc<<<g_grid, 256, G_SMEM_TOTAL>>>(pAhi, pAlo, pBhi, pBlo, b_k, pK);
    // V projection
    conv_act<<<act_blocks, 256>>>((const float4*)v,
                                  (__nv_bfloat162*)pAhi, (__nv_bfloat162*)pAlo);
    conv_wt<<<wt_grid, wt_block>>>(w_v, pBhi, pBlo);
    gemm_tc<<<g_grid, 256, G_SMEM_TOTAL>>>(pAhi, pAlo, pBhi, pBlo, b_v, pV);

    // Attention
    dim3 agrid(SEQ / 64, BATCH * NHEAD);                    // (32, 32)
    attn_kernel<<<agrid, 256, ATT_SMEM_BYTES>>>(msk);

    // Output projection
    conv_act<<<act_blocks, 256>>>((const float4*)pO,
                                  (__nv_bfloat162*)pAhi, (__nv_bfloat162*)pAlo);
    conv_wt<<<wt_grid, wt_block>>>(w_o, pBhi, pBlo);
    gemm_tc<<<g_grid, 256, G_SMEM_TOTAL>>>(pAhi, pAlo, pBhi, pBlo, b_o, out);
}

// round 9
// speedup vs baseline: 1.9709x; 1.5184x over previous
#include <cuda_runtime.h>
#include <cuda_bf16.h>
#include <cstdint>

// Problem constants
#define MODEL_DIM 1024
#define NHEAD     16
#define HDIM      64
#define BATCH     2
#define SEQ       2048
#define MROWS     (BATCH * SEQ)   // 4096

// ===========================================================================
// Scratch (device globals — allocation-free per harness rules)
// ===========================================================================
__device__ float g_O[MROWS * MODEL_DIM];
// bf16 split buffers for GEMM A operand (reused across the 4 GEMMs)
__device__ __nv_bfloat16 g_Ahi[MROWS * MODEL_DIM];
__device__ __nv_bfloat16 g_Alo[MROWS * MODEL_DIM];
__device__ __nv_bfloat16 g_Bhi[MODEL_DIM * MODEL_DIM];   // W^T hi  [n][k]
__device__ __nv_bfloat16 g_Blo[MODEL_DIM * MODEL_DIM];   // W^T lo  [n][k]
// Projected Q/K/V as bf16 hi/lo (written by GEMM epilogue)
__device__ __nv_bfloat16 g_Qhi[MROWS * MODEL_DIM];
__device__ __nv_bfloat16 g_Qlo[MROWS * MODEL_DIM];
__device__ __nv_bfloat16 g_Khi[MROWS * MODEL_DIM];
__device__ __nv_bfloat16 g_Klo[MROWS * MODEL_DIM];
__device__ __nv_bfloat16 g_Vhi[MROWS * MODEL_DIM];
__device__ __nv_bfloat16 g_Vlo[MROWS * MODEL_DIM];
// Additive mask bias (0 or -1e4) in bf16
__device__ __nv_bfloat16 g_mb[SEQ * SEQ];

// ===========================================================================
// Helpers (base sm_103 ISA: ldmatrix + mma.sync)
// ===========================================================================
__device__ __forceinline__ uint32_t smem_u32(const void* p) {
    uint32_t a;
    asm("{ .reg .u64 t; cvta.to.shared.u64 t, %1; cvt.u32.u64 %0, t; }"
        : "=r"(a) : "l"(p));
    return a;
}

#define SMEM_SWIZZLE_128B(o) ((o) ^ (((o) >> 3) & 0x70))

__device__ __forceinline__ void ldsm_x4(uint32_t* r, uint32_t addr) {
    asm volatile("ldmatrix.sync.aligned.m8n8.x4.shared.b16 {%0,%1,%2,%3}, [%4];"
                 : "=r"(r[0]), "=r"(r[1]), "=r"(r[2]), "=r"(r[3]) : "r"(addr));
}
__device__ __forceinline__ void ldsm_x4_t(uint32_t* r, uint32_t addr) {
    asm volatile("ldmatrix.sync.aligned.m8n8.x4.trans.shared.b16 {%0,%1,%2,%3}, [%4];"
                 : "=r"(r[0]), "=r"(r[1]), "=r"(r[2]), "=r"(r[3]) : "r"(addr));
}
__device__ __forceinline__ void ldsm_x2(uint32_t* r, uint32_t addr) {
    asm volatile("ldmatrix.sync.aligned.m8n8.x2.shared.b16 {%0,%1}, [%2];"
                 : "=r"(r[0]), "=r"(r[1]) : "r"(addr));
}
__device__ __forceinline__ void mma16816(float* c, const uint32_t* a,
                                         const uint32_t* b) {
    asm volatile(
        "mma.sync.aligned.m16n8k16.row.col.f32.bf16.bf16.f32 "
        "{%0,%1,%2,%3}, {%4,%5,%6,%7}, {%8,%9}, {%0,%1,%2,%3};"
        : "+f"(c[0]), "+f"(c[1]), "+f"(c[2]), "+f"(c[3])
        : "r"(a[0]), "r"(a[1]), "r"(a[2]), "r"(a[3]), "r"(b[0]), "r"(b[1]));
}

// Split two fp32 into packed bf16x2 hi and lo (lo = residual)
__device__ __forceinline__ void split_pack(uint32_t& h, uint32_t& l,
                                           float x, float y) {
    __nv_bfloat162 h2 = __floats2bfloat162_rn(x, y);   // .x low = x
    float lx = x - __bfloat162float(h2.x);
    float ly = y - __bfloat162float(h2.y);
    __nv_bfloat162 l2 = __floats2bfloat162_rn(lx, ly);
    h = *reinterpret_cast<uint32_t*>(&h2);
    l = *reinterpret_cast<uint32_t*>(&l2);
}

// ===========================================================================
// fp32 -> bf16 hi/lo split for activations (layout preserved)
// ===========================================================================
__global__ __launch_bounds__(256) void conv_act(
    const float4* __restrict__ X,
    __nv_bfloat162* __restrict__ hi2, __nv_bfloat162* __restrict__ lo2) {
    int i = blockIdx.x * 256 + threadIdx.x;
    float4 x = X[i];
    __nv_bfloat16 h0 = __float2bfloat16_rn(x.x);
    __nv_bfloat16 h1 = __float2bfloat16_rn(x.y);
    __nv_bfloat16 h2 = __float2bfloat16_rn(x.z);
    __nv_bfloat16 h3 = __float2bfloat16_rn(x.w);
    __nv_bfloat16 l0 = __float2bfloat16_rn(x.x - __bfloat162float(h0));
    __nv_bfloat16 l1 = __float2bfloat16_rn(x.y - __bfloat162float(h1));
    __nv_bfloat16 l2 = __float2bfloat16_rn(x.z - __bfloat162float(h2));
    __nv_bfloat16 l3 = __float2bfloat16_rn(x.w - __bfloat162float(h3));
    hi2[2 * i + 0] = __nv_bfloat162(h0, h1);
    hi2[2 * i + 1] = __nv_bfloat162(h2, h3);
    lo2[2 * i + 0] = __nv_bfloat162(l0, l1);
    lo2[2 * i + 1] = __nv_bfloat162(l2, l3);
}

// fp32 W[k][n] -> transposed bf16 hi/lo Wt[n][k]  (smem tile transpose)
__global__ __launch_bounds__(256) void conv_wt(
    const float* __restrict__ W,
    __nv_bfloat16* __restrict__ Thi, __nv_bfloat16* __restrict__ Tlo) {
    __shared__ float t[32][33];
    int n0 = blockIdx.x * 32, k0 = blockIdx.y * 32;
    int tx = threadIdx.x, ty = threadIdx.y;   // block (32, 8)
#pragma unroll
    for (int i = 0; i < 4; i++)
        t[ty + 8 * i][tx] = W[(size_t)(k0 + ty + 8 * i) * MODEL_DIM + n0 + tx];
    __syncthreads();
#pragma unroll
    for (int i = 0; i < 4; i++) {
        float x = t[tx][ty + 8 * i];
        __nv_bfloat16 h = __float2bfloat16_rn(x);
        __nv_bfloat16 l = __float2bfloat16_rn(x - __bfloat162float(h));
        size_t off = (size_t)(n0 + ty + 8 * i) * MODEL_DIM + k0 + tx;
        Thi[off] = h;
        Tlo[off] = l;
    }
}

// int32 mask -> bf16 additive bias (0 / -1e4)
__global__ __launch_bounds__(256) void conv_mask(
    const int4* __restrict__ m, __nv_bfloat162* __restrict__ out2) {
    int i = blockIdx.x * 256 + threadIdx.x;   // SEQ*SEQ/4 threads
    int4 v = m[i];
    const float NEG = -1e4f;
    out2[2 * i + 0] = __floats2bfloat162_rn(v.x ? 0.f : NEG, v.y ? 0.f : NEG);
    out2[2 * i + 1] = __floats2bfloat162_rn(v.z ? 0.f : NEG, v.w ? 0.f : NEG);
}

// ===========================================================================
// HMMA GEMM: C = A @ W + bias.  bf16x3 split, fp32 accumulate.
// CTA 128x128, BK=64, 256 threads (8 warps, warp tile 64x32), SW128 smem.
// SPLIT_OUT: write bf16 hi/lo pair instead of fp32.
// ===========================================================================
#define G_OFF_AH   0
#define G_OFF_AL   16384
#define G_OFF_BH   32768
#define G_OFF_BL   49152
#define G_SMEM_TOTAL 65536

__device__ __forceinline__ void load_tile_bf16(
    char* smem, int dst_off, const __nv_bfloat16* __restrict__ src,
    int row0, int k0, int tid) {
#pragma unroll
    for (int it = 0; it < 4; it++) {
        int t = tid + it * 256;
        int row = t >> 3;
        int seg = t & 7;
        uint4 v = *(const uint4*)(src + (size_t)(row0 + row) * MODEL_DIM + k0 + seg * 8);
        *(uint4*)(smem + dst_off + SMEM_SWIZZLE_128B(row * 128 + seg * 16)) = v;
    }
}

template <bool SPLIT_OUT>
__global__ __launch_bounds__(256) void gemm_tc(
    const __nv_bfloat16* __restrict__ Ahi, const __nv_bfloat16* __restrict__ Alo,
    const __nv_bfloat16* __restrict__ Bhi, const __nv_bfloat16* __restrict__ Blo,
    const float* __restrict__ bias, float* __restrict__ C,
    __nv_bfloat16* __restrict__ Chi, __nv_bfloat16* __restrict__ Clo) {
    extern __shared__ char smem[];
    uint32_t sb = smem_u32(smem);
    const int tid = threadIdx.x;
    const int wid = tid >> 5;
    const int lane = tid & 31;
    const int warp_m = wid >> 2;
    const int warp_n = wid & 3;
    const int m0 = blockIdx.y * 128;
    const int n0 = blockIdx.x * 128;

    float acc[4][4][4];
#pragma unroll
    for (int i = 0; i < 4; i++)
#pragma unroll
        for (int j = 0; j < 4; j++)
#pragma unroll
            for (int f = 0; f < 4; f++) acc[i][j][f] = 0.f;

    const int a_row = lane & 15;
    const int a_kb = (lane >> 4) << 4;
    const int b_row = lane & 7;
    const int b_kb = ((lane >> 3) & 1) << 4;

    for (int ck = 0; ck < MODEL_DIM / 64; ck++) {
        int k0 = ck * 64;
        load_tile_bf16(smem, G_OFF_AH, Ahi, m0, k0, tid);
        load_tile_bf16(smem, G_OFF_AL, Alo, m0, k0, tid);
        load_tile_bf16(smem, G_OFF_BH, Bhi, n0, k0, tid);
        load_tile_bf16(smem, G_OFF_BL, Blo, n0, k0, tid);
        __syncthreads();

#pragma unroll
        for (int ks = 0; ks < 4; ks++) {
            uint32_t ah[4][4], al[4][4], bh[4][2], bl[4][2];
#pragma unroll
            for (int mt = 0; mt < 4; mt++) {
                int row = warp_m * 64 + mt * 16 + a_row;
                uint32_t sw = SMEM_SWIZZLE_128B(row * 128 + ks * 32 + a_kb);
                ldsm_x4(ah[mt], sb + G_OFF_AH + sw);
                ldsm_x4(al[mt], sb + G_OFF_AL + sw);
            }
#pragma unroll
            for (int nt = 0; nt < 4; nt++) {
                int row = warp_n * 32 + nt * 8 + b_row;
                uint32_t sw = SMEM_SWIZZLE_128B(row * 128 + ks * 32 + b_kb);
                ldsm_x2(bh[nt], sb + G_OFF_BH + sw);
                ldsm_x2(bl[nt], sb + G_OFF_BL + sw);
            }
#pragma unroll
            for (int mt = 0; mt < 4; mt++)
#pragma unroll
                for (int nt = 0; nt < 4; nt++) {
                    mma16816(acc[mt][nt], ah[mt], bh[nt]);
                    mma16816(acc[mt][nt], ah[mt], bl[nt]);
                    mma16816(acc[mt][nt], al[mt], bh[nt]);
                }
        }
        __syncthreads();
    }

    const int g = lane >> 2;
    const int tq = (lane & 3) * 2;
#pragma unroll
    for (int mt = 0; mt < 4; mt++)
#pragma unroll
        for (int nt = 0; nt < 4; nt++) {
            int m = m0 + warp_m * 64 + mt * 16 + g;
            int n = n0 + warp_n * 32 + nt * 8 + tq;
            float2 bb = *(const float2*)(bias + n);
            float v00 = acc[mt][nt][0] + bb.x, v01 = acc[mt][nt][1] + bb.y;
            float v10 = acc[mt][nt][2] + bb.x, v11 = acc[mt][nt][3] + bb.y;
            if (SPLIT_OUT) {
                uint32_t h0, l0v, h1, l1v;
                split_pack(h0, l0v, v00, v01);
                split_pack(h1, l1v, v10, v11);
                *(uint32_t*)(Chi + (size_t)m * MODEL_DIM + n) = h0;
                *(uint32_t*)(Clo + (size_t)m * MODEL_DIM + n) = l0v;
                *(uint32_t*)(Chi + (size_t)(m + 8) * MODEL_DIM + n) = h1;
                *(uint32_t*)(Clo + (size_t)(m + 8) * MODEL_DIM + n) = l1v;
            } else {
                *(float2*)(C + (size_t)m * MODEL_DIM + n) = make_float2(v00, v01);
                *(float2*)(C + (size_t)(m + 8) * MODEL_DIM + n) = make_float2(v10, v11);
            }
        }
}

// ===========================================================================
// Tensor-core flash attention (HMMA, bf16x3 split everywhere).
// Block = 128 threads (4 warps) = 64 query rows for one (b,h).
// Warp w owns rows w*16..w*16+15.  Key tiles of 64.
// Smem: Khi/Klo/Vhi/Vlo 64x64 bf16 tiles, SW128 (32KB); Q staged through the
// same region before the main loop.
// ===========================================================================
#define AT_OFF_KH 0
#define AT_OFF_KL 8192
#define AT_OFF_VH 16384
#define AT_OFF_VL 24576
#define AT_SMEM   32768

__global__ __launch_bounds__(128) void attn_tc() {
    extern __shared__ char smc[];
    uint32_t sb = smem_u32(smc);
    const int tid = threadIdx.x;
    const int lane = tid & 31;
    const int w = tid >> 5;
    const int qt = blockIdx.x;            // 0..31 (64-row q tiles)
    const int bh = blockIdx.y;
    const int b = bh >> 4, h = bh & 15;
    const size_t qtok = (size_t)(b * SEQ + qt * 64);
    const size_t ktok = (size_t)(b * SEQ);

    // ---- stage Q (hi at KH region, lo at KL region), extract fragments ----
    {
        const __nv_bfloat16* Qh = g_Qhi + qtok * MODEL_DIM + h * HDIM;
        const __nv_bfloat16* Ql = g_Qlo + qtok * MODEL_DIM + h * HDIM;
#pragma unroll
        for (int i = 0; i < 4; i++) {
            int t = tid + i * 128;
            int r = t >> 3, s8 = t & 7;
            uint32_t dst = SMEM_SWIZZLE_128B(r * 128 + s8 * 16);
            *(uint4*)(smc + AT_OFF_KH + dst) =
                *(const uint4*)(Qh + (size_t)r * MODEL_DIM + s8 * 8);
            *(uint4*)(smc + AT_OFF_KL + dst) =
                *(const uint4*)(Ql + (size_t)r * MODEL_DIM + s8 * 8);
        }
    }
    __syncthreads();
    uint32_t qh[4][4], ql[4][4];
    {
        int ar = lane & 15, akb = (lane >> 4) << 4;
#pragma unroll
        for (int ks = 0; ks < 4; ks++) {
            uint32_t off = SMEM_SWIZZLE_128B((w * 16 + ar) * 128 + ks * 32 + akb);
            ldsm_x4(qh[ks], sb + AT_OFF_KH + off);
            ldsm_x4(ql[ks], sb + AT_OFF_KL + off);
        }
    }
    __syncthreads();

    float m0 = -1e30f, m1 = -1e30f, l0 = 0.f, l1 = 0.f;
    float o[8][4];
#pragma unroll
    for (int i = 0; i < 8; i++)
#pragma unroll
        for (int j = 0; j < 4; j++) o[i][j] = 0.f;

    const __nv_bfloat16* Kh = g_Khi + ktok * MODEL_DIM + h * HDIM;
    const __nv_bfloat16* Kl = g_Klo + ktok * MODEL_DIM + h * HDIM;
    const __nv_bfloat16* Vh = g_Vhi + ktok * MODEL_DIM + h * HDIM;
    const __nv_bfloat16* Vl = g_Vlo + ktok * MODEL_DIM + h * HDIM;

    const int g = lane >> 2;
    const int tq2 = (lane & 3) * 2;
    // B-frag lane addressing for K (non-trans)
    const int krow_in = ((lane >> 4) << 3) + (lane & 7);
    const int kkb = ((lane >> 3) & 1) << 4;
    // B-frag lane addressing for V (trans)
    const int vk_in = (((lane >> 3) & 1) << 3) + (lane & 7);
    const int vd_in = (lane >> 4) << 3;

    const __nv_bfloat16* mbrow = g_mb + (size_t)(qt * 64 + w * 16 + g) * SEQ + tq2;

    for (int kt = 0; kt < SEQ / 64; kt++) {
        // load K/V tiles
        {
            const size_t toff = (size_t)(kt * 64);
#pragma unroll
            for (int i = 0; i < 4; i++) {
                int t = tid + i * 128;
                int r = t >> 3, s8 = t & 7;
                uint32_t dst = SMEM_SWIZZLE_128B(r * 128 + s8 * 16);
                size_t src = (toff + r) * MODEL_DIM + s8 * 8;
                *(uint4*)(smc + AT_OFF_KH + dst) = *(const uint4*)(Kh + src);
                *(uint4*)(smc + AT_OFF_KL + dst) = *(const uint4*)(Kl + src);
                *(uint4*)(smc + AT_OFF_VH + dst) = *(const uint4*)(Vh + src);
                *(uint4*)(smc + AT_OFF_VL + dst) = *(const uint4*)(Vl + src);
            }
        }
        __syncthreads();

        // ---- S = Q K^T (bf16x3) ----
        float s[8][4];
#pragma unroll
        for (int i = 0; i < 8; i++)
#pragma unroll
            for (int j = 0; j < 4; j++) s[i][j] = 0.f;

#pragma unroll
        for (int ks = 0; ks < 4; ks++) {
#pragma unroll
            for (int ntp = 0; ntp < 4; ntp++) {
                uint32_t off = SMEM_SWIZZLE_128B((ntp * 16 + krow_in) * 128 +
                                                 ks * 32 + kkb);
                uint32_t bhf[4], blf[4];
                ldsm_x4(bhf, sb + AT_OFF_KH + off);
                ldsm_x4(blf, sb + AT_OFF_KL + off);
                mma16816(s[2 * ntp], qh[ks], bhf + 0);
                mma16816(s[2 * ntp], qh[ks], blf + 0);
                mma16816(s[2 * ntp], ql[ks], bhf + 0);
                mma16816(s[2 * ntp + 1], qh[ks], bhf + 2);
                mma16816(s[2 * ntp + 1], qh[ks], blf + 2);
                mma16816(s[2 * ntp + 1], ql[ks], bhf + 2);
            }
        }

        // ---- scale + additive mask bias ----
        const float scale = 0.125f;
        const __nv_bfloat16* mb = mbrow + kt * 64;
#pragma unroll
        for (int nt = 0; nt < 8; nt++) {
            uint32_t u0 = *(const uint32_t*)(mb + nt * 8);
            uint32_t u1 = *(const uint32_t*)(mb + 8 * SEQ + nt * 8);
            float2 f0 = __bfloat1622float2(*reinterpret_cast<__nv_bfloat162*>(&u0));
            float2 f1 = __bfloat1622float2(*reinterpret_cast<__nv_bfloat162*>(&u1));
            s[nt][0] = s[nt][0] * scale + f0.x;
            s[nt][1] = s[nt][1] * scale + f0.y;
            s[nt][2] = s[nt][2] * scale + f1.x;
            s[nt][3] = s[nt][3] * scale + f1.y;
        }

        // ---- online softmax (rows g and g+8; quad shfl reductions) ----
        float rm0 = -1e30f, rm1 = -1e30f;
#pragma unroll
        for (int nt = 0; nt < 8; nt++) {
            rm0 = fmaxf(rm0, fmaxf(s[nt][0], s[nt][1]));
            rm1 = fmaxf(rm1, fmaxf(s[nt][2], s[nt][3]));
        }
        rm0 = fmaxf(rm0, __shfl_xor_sync(0xffffffffu, rm0, 1));
        rm0 = fmaxf(rm0, __shfl_xor_sync(0xffffffffu, rm0, 2));
        rm1 = fmaxf(rm1, __shfl_xor_sync(0xffffffffu, rm1, 1));
        rm1 = fmaxf(rm1, __shfl_xor_sync(0xffffffffu, rm1, 2));
        float mn0 = fmaxf(m0, rm0), mn1 = fmaxf(m1, rm1);
        float a0 = __expf(m0 - mn0), a1 = __expf(m1 - mn1);
        float rs0 = 0.f, rs1 = 0.f;
#pragma unroll
        for (int nt = 0; nt < 8; nt++) {
            s[nt][0] = __expf(s[nt][0] - mn0);
            s[nt][1] = __expf(s[nt][1] - mn0);
            s[nt][2] = __expf(s[nt][2] - mn1);
            s[nt][3] = __expf(s[nt][3] - mn1);
            rs0 += s[nt][0] + s[nt][1];
            rs1 += s[nt][2] + s[nt][3];
        }
        rs0 += __shfl_xor_sync(0xffffffffu, rs0, 1);
        rs0 += __shfl_xor_sync(0xffffffffu, rs0, 2);
        rs1 += __shfl_xor_sync(0xffffffffu, rs1, 1);
        rs1 += __shfl_xor_sync(0xffffffffu, rs1, 2);
        l0 = l0 * a0 + rs0; m0 = mn0;
        l1 = l1 * a1 + rs1; m1 = mn1;
#pragma unroll
        for (int nd = 0; nd < 8; nd++) {
            o[nd][0] *= a0; o[nd][1] *= a0;
            o[nd][2] *= a1; o[nd][3] *= a1;
        }

        // ---- pack P into A fragments (hi/lo), in registers ----
        uint32_t ph[4][4], pl[4][4];
#pragma unroll
        for (int j = 0; j < 4; j++) {
            split_pack(ph[j][0], pl[j][0], s[2 * j][0], s[2 * j][1]);
            split_pack(ph[j][1], pl[j][1], s[2 * j][2], s[2 * j][3]);
            split_pack(ph[j][2], pl[j][2], s[2 * j + 1][0], s[2 * j + 1][1]);
            split_pack(ph[j][3], pl[j][3], s[2 * j + 1][2], s[2 * j + 1][3]);
        }

        // ---- O += P V (bf16x3) ----
#pragma unroll
        for (int j = 0; j < 4; j++) {
#pragma unroll
            for (int ndp = 0; ndp < 4; ndp++) {
                uint32_t off = SMEM_SWIZZLE_128B((j * 16 + vk_in) * 128 +
                                                 (ndp * 16 + vd_in) * 2);
                uint32_t vh4[4], vl4[4];
                ldsm_x4_t(vh4, sb + AT_OFF_VH + off);
                ldsm_x4_t(vl4, sb + AT_OFF_VL + off);
                mma16816(o[2 * ndp], ph[j], vh4 + 0);
                mma16816(o[2 * ndp], ph[j], vl4 + 0);
                mma16816(o[2 * ndp], pl[j], vh4 + 0);
                mma16816(o[2 * ndp + 1], ph[j], vh4 + 2);
                mma16816(o[2 * ndp + 1], ph[j], vl4 + 2);
                mma16816(o[2 * ndp + 1], pl[j], vh4 + 2);
            }
        }
        __syncthreads();
    }

    // ---- epilogue: normalize and write fp32 ----
    float i0 = 1.f / l0, i1 = 1.f / l1;
    float* Og = g_O + (qtok + w * 16 + g) * MODEL_DIM + h * HDIM + tq2;
#pragma unroll
    for (int nd = 0; nd < 8; nd++) {
        *(float2*)(Og + nd * 8) = make_float2(o[nd][0] * i0, o[nd][1] * i0);
        *(float2*)(Og + 8 * MODEL_DIM + nd * 8) =
            make_float2(o[nd][2] * i1, o[nd][3] * i1);
    }
}

// ===========================================================================
// Launch
// ===========================================================================
extern "C" void kernel_launch(void* const* d_in, const int* in_sizes, int n_in,
                              void* d_out, int out_size) {
    const float* q   = (const float*)d_in[0];
    const float* k   = (const float*)d_in[1];
    const float* v   = (const float*)d_in[2];
    const int*   msk = (const int*)  d_in[3];
    const float* w_q = (const float*)d_in[4];
    const float* b_q = (const float*)d_in[5];
    const float* w_k = (const float*)d_in[6];
    const float* b_k = (const float*)d_in[7];
    const float* w_v = (const float*)d_in[8];
    const float* b_v = (const float*)d_in[9];
    const float* w_o = (const float*)d_in[10];
    const float* b_o = (const float*)d_in[11];
    float* out = (float*)d_out;

    float* pO;
    __nv_bfloat16 *pAhi, *pAlo, *pBhi, *pBlo;
    __nv_bfloat16 *pQh, *pQl, *pKh, *pKl, *pVh, *pVl, *pMB;
    cudaGetSymbolAddress((void**)&pO, g_O);
    cudaGetSymbolAddress((void**)&pAhi, g_Ahi);
    cudaGetSymbolAddress((void**)&pAlo, g_Alo);
    cudaGetSymbolAddress((void**)&pBhi, g_Bhi);
    cudaGetSymbolAddress((void**)&pBlo, g_Blo);
    cudaGetSymbolAddress((void**)&pQh, g_Qhi);
    cudaGetSymbolAddress((void**)&pQl, g_Qlo);
    cudaGetSymbolAddress((void**)&pKh, g_Khi);
    cudaGetSymbolAddress((void**)&pKl, g_Klo);
    cudaGetSymbolAddress((void**)&pVh, g_Vhi);
    cudaGetSymbolAddress((void**)&pVl, g_Vlo);
    cudaGetSymbolAddress((void**)&pMB, g_mb);

    cudaFuncSetAttribute(gemm_tc<true>,
                         cudaFuncAttributeMaxDynamicSharedMemorySize, G_SMEM_TOTAL);
    cudaFuncSetAttribute(gemm_tc<false>,
                         cudaFuncAttributeMaxDynamicSharedMemorySize, G_SMEM_TOTAL);

    const int act_blocks = (MROWS * MODEL_DIM / 4) / 256;   // 4096
    dim3 wt_grid(MODEL_DIM / 32, MODEL_DIM / 32);
    dim3 wt_block(32, 8);
    dim3 g_grid(MODEL_DIM / 128, MROWS / 128);              // (8, 32)

    // mask -> additive bias (independent of projections)
    conv_mask<<<(SEQ * SEQ / 4) / 256, 256>>>((const int4*)msk,
                                              (__nv_bfloat162*)pMB);

    // Q projection -> bf16 hi/lo
    conv_act<<<act_blocks, 256>>>((const float4*)q,
                                  (__nv_bfloat162*)pAhi, (__nv_bfloat162*)pAlo);
    conv_wt<<<wt_grid, wt_block>>>(w_q, pBhi, pBlo);
    gemm_tc<true><<<g_grid, 256, G_SMEM_TOTAL>>>(pAhi, pAlo, pBhi, pBlo, b_q,
                                                 nullptr, pQh, pQl);
    // K projection -> bf16 hi/lo
    conv_act<<<act_blocks, 256>>>((const float4*)k,
                                  (__nv_bfloat162*)pAhi, (__nv_bfloat162*)pAlo);
    conv_wt<<<wt_grid, wt_block>>>(w_k, pBhi, pBlo);
    gemm_tc<true><<<g_grid, 256, G_SMEM_TOTAL>>>(pAhi, pAlo, pBhi, pBlo, b_k,
                                                 nullptr, pKh, pKl);
    // V projection -> bf16 hi/lo
    conv_act<<<act_blocks, 256>>>((const float4*)v,
                                  (__nv_bfloat162*)pAhi, (__nv_bfloat162*)pAlo);
    conv_wt<<<wt_grid, wt_block>>>(w_v, pBhi, pBlo);
    gemm_tc<true><<<g_grid, 256, G_SMEM_TOTAL>>>(pAhi, pAlo, pBhi, pBlo, b_v,
                                                 nullptr, pVh, pVl);

    // Tensor-core flash attention
    dim3 agrid(SEQ / 64, BATCH * NHEAD);                    // (32, 32)
    attn_tc<<<agrid, 128, AT_SMEM>>>();

    // Output projection (fp32 out)
    conv_act<<<act_blocks, 256>>>((const float4*)pO,
                                  (__nv_bfloat162*)pAhi, (__nv_bfloat162*)pAlo);
    conv_wt<<<wt_grid, wt_block>>>(w_o, pBhi, pBlo);
    gemm_tc<false><<<g_grid, 256, G_SMEM_TOTAL>>>(pAhi, pAlo, pBhi, pBlo, b_o,
                                                  out, nullptr, nullptr);
}